// round 1
// baseline (speedup 1.0000x reference)
#include <cuda_runtime.h>
#include <cuda_bf16.h>
#include <stddef.h>

#define DD 128
#define NMAX 50176
#define EMAX 409600

// ---------------- device scratch (static, no runtime allocation) ----------------
__device__ float g_qa[NMAX * DD];
__device__ float g_ka[NMAX * DD];
__device__ float g_qb[NMAX * DD];
__device__ float g_kb[NMAX * DD];
__device__ float g_wtp[NMAX * DD];
__device__ float g_wxp[NMAX * DD];
__device__ float g_ea[EMAX];
__device__ float g_eb[EMAX];
__device__ int   g_deg[NMAX];
__device__ int   g_off[NMAX + 1];
__device__ int   g_cur[NMAX];
__device__ int   g_scol[EMAX];
__device__ int   g_seid[EMAX];

// ---------------- packed f32x2 helpers ----------------
__device__ __forceinline__ unsigned long long dup2(float v) {
    unsigned long long r;
    asm("mov.b64 %0, {%1, %1};" : "=l"(r) : "f"(v));
    return r;
}
__device__ __forceinline__ void fma2(unsigned long long& c, unsigned long long a,
                                     unsigned long long b) {
    asm("fma.rn.f32x2 %0, %1, %2, %0;" : "+l"(c) : "l"(a), "l"(b));
}
__device__ __forceinline__ float2 unpack2(unsigned long long v) {
    float2 r;
    asm("mov.b64 {%0, %1}, %2;" : "=f"(r.x), "=f"(r.y) : "l"(v));
    return r;
}

__device__ __forceinline__ float* dest_of(int which) {
    switch (which) {
        case 0: return g_qa;
        case 1: return g_ka;
        case 2: return g_wtp;
        case 3: return g_qb;
        case 4: return g_kb;
        default: return g_wxp;
    }
}

// ---------------- projection GEMM: out[n,d] = sum_k in[n,k]*W[d,k] (+ bias[d]) ----
// Block tile: 128 rows x 128 cols, full K=128. 256 threads, micro-tile 4 rows x 16 cols,
// packed f32x2 accumulators (column pairs).
__global__ void __launch_bounds__(256, 1)
proj_kernel(const float* __restrict__ in, const float* __restrict__ W,
            const float* __restrict__ bias, int which, int N) {
    extern __shared__ float sm[];
    float* ins = sm;              // [128][132] padded
    float* Ws  = sm + 128 * 132;  // [k][d] transposed weight

    const int tid  = threadIdx.x;
    const int row0 = blockIdx.x * 128;

    // Load W transposed into smem: Ws[k*128+d] = W[d*128+k]
    for (int t = tid; t < 128 * 32; t += 256) {
        int kq = t >> 7;    // 0..31
        int d  = t & 127;
        float4 w = *(const float4*)(W + d * DD + kq * 4);
        Ws[(kq * 4 + 0) * DD + d] = w.x;
        Ws[(kq * 4 + 1) * DD + d] = w.y;
        Ws[(kq * 4 + 2) * DD + d] = w.z;
        Ws[(kq * 4 + 3) * DD + d] = w.w;
    }
    // Load input tile (zero-padded past N)
    for (int t = tid; t < 128 * 32; t += 256) {
        int r  = t >> 5;    // 0..127
        int kq = t & 31;
        int gr = row0 + r;
        float4 v = make_float4(0.f, 0.f, 0.f, 0.f);
        if (gr < N) v = *(const float4*)(in + (size_t)gr * DD + kq * 4);
        *(float4*)(ins + r * 132 + kq * 4) = v;
    }
    __syncthreads();

    const int tr = tid >> 3;  // 0..31 -> rows tr*4 .. tr*4+3
    const int tc = tid & 7;   // 0..7  -> cols tc*16 .. tc*16+15

    unsigned long long acc[4][8];
#pragma unroll
    for (int r = 0; r < 4; r++)
#pragma unroll
        for (int c = 0; c < 8; c++) acc[r][c] = 0ull;

    const float* ap = ins + (tr * 4) * 132;

#pragma unroll 2
    for (int k = 0; k < DD; k++) {
        unsigned long long pa[4];
        pa[0] = dup2(ap[k]);
        pa[1] = dup2(ap[132 + k]);
        pa[2] = dup2(ap[264 + k]);
        pa[3] = dup2(ap[396 + k]);
        const ulonglong2* wr = (const ulonglong2*)(Ws + k * DD + tc * 16);
        ulonglong2 w0 = wr[0], w1 = wr[1], w2 = wr[2], w3 = wr[3];
        unsigned long long bb[8];
        bb[0] = w0.x; bb[1] = w0.y; bb[2] = w1.x; bb[3] = w1.y;
        bb[4] = w2.x; bb[5] = w2.y; bb[6] = w3.x; bb[7] = w3.y;
#pragma unroll
        for (int r = 0; r < 4; r++)
#pragma unroll
            for (int c = 0; c < 8; c++) fma2(acc[r][c], pa[r], bb[c]);
    }

    float bvals[16];
    if (bias != nullptr) {
#pragma unroll
        for (int q = 0; q < 4; q++) {
            float4 b4 = *(const float4*)(bias + tc * 16 + q * 4);
            bvals[q * 4 + 0] = b4.x;
            bvals[q * 4 + 1] = b4.y;
            bvals[q * 4 + 2] = b4.z;
            bvals[q * 4 + 3] = b4.w;
        }
    } else {
#pragma unroll
        for (int q = 0; q < 16; q++) bvals[q] = 0.f;
    }

    float* out = dest_of(which);
#pragma unroll
    for (int r = 0; r < 4; r++) {
        int gr = row0 + tr * 4 + r;
        if (gr >= N) continue;
        float o[16];
#pragma unroll
        for (int c = 0; c < 8; c++) {
            float2 u = unpack2(acc[r][c]);
            o[2 * c]     = u.x + bvals[2 * c];
            o[2 * c + 1] = u.y + bvals[2 * c + 1];
        }
        float4* op = (float4*)(out + (size_t)gr * DD + tc * 16);
        op[0] = make_float4(o[0], o[1], o[2], o[3]);
        op[1] = make_float4(o[4], o[5], o[6], o[7]);
        op[2] = make_float4(o[8], o[9], o[10], o[11]);
        op[3] = make_float4(o[12], o[13], o[14], o[15]);
    }
}

// ---------------- CSR construction ----------------
__global__ void zero_deg_kernel(int N) {
    int i = blockIdx.x * blockDim.x + threadIdx.x;
    if (i < N) g_deg[i] = 0;
}

__global__ void count_deg_kernel(const int* __restrict__ rows, int E) {
    int e = blockIdx.x * blockDim.x + threadIdx.x;
    if (e < E) atomicAdd(&g_deg[rows[e]], 1);
}

// single-block exclusive scan of g_deg -> g_off (and g_cur copy)
__global__ void scan_kernel(int N) {
    __shared__ int sh[1024];
    __shared__ int carry;
    int tid = threadIdx.x;
    if (tid == 0) carry = 0;
    __syncthreads();
    for (int base = 0; base < N; base += 1024) {
        int i = base + tid;
        int v = (i < N) ? g_deg[i] : 0;
        sh[tid] = v;
        __syncthreads();
        for (int off = 1; off < 1024; off <<= 1) {
            int tv = 0;
            if (tid >= off) tv = sh[tid - off];
            __syncthreads();
            if (tid >= off) sh[tid] += tv;
            __syncthreads();
        }
        int excl = sh[tid] - v;
        int c = carry;
        if (i < N) {
            g_off[i] = c + excl;
            g_cur[i] = c + excl;
        }
        int total = sh[1023];
        __syncthreads();
        if (tid == 0) carry = c + total;
        __syncthreads();
    }
    if (tid == 0) g_off[N] = carry;
}

__global__ void scatter_kernel(const int* __restrict__ rows, const int* __restrict__ cols,
                               int E) {
    int e = blockIdx.x * blockDim.x + threadIdx.x;
    if (e < E) {
        int p = atomicAdd(&g_cur[rows[e]], 1);
        g_scol[p] = cols[e];
        g_seid[p] = e;
    }
}

// ---------------- per-edge exp(score): one warp per edge ----------------
__global__ void scores_kernel(const int* __restrict__ rows, const int* __restrict__ cols,
                              int E) {
    int w    = blockIdx.x * (blockDim.x >> 5) + (threadIdx.x >> 5);
    int lane = threadIdx.x & 31;
    if (w >= E) return;
    int i = rows[w];
    int j = cols[w];
    const float4 qa = *(const float4*)(g_qa + (size_t)i * DD + lane * 4);
    const float4 ka = *(const float4*)(g_ka + (size_t)j * DD + lane * 4);
    const float4 qb = *(const float4*)(g_qb + (size_t)i * DD + lane * 4);
    const float4 kb = *(const float4*)(g_kb + (size_t)j * DD + lane * 4);
    float sa = qa.x * ka.x + qa.y * ka.y + qa.z * ka.z + qa.w * ka.w;
    float sb = qb.x * kb.x + qb.y * kb.y + qb.z * kb.z + qb.w * kb.w;
#pragma unroll
    for (int off = 16; off > 0; off >>= 1) {
        sa += __shfl_xor_sync(0xffffffffu, sa, off);
        sb += __shfl_xor_sync(0xffffffffu, sb, off);
    }
    if (lane == 0) {
        const float s = 0.08838834764831845f;  // 1/sqrt(128)
        g_ea[w] = expf(sa * s);
        g_eb[w] = expf(sb * s);
    }
}

// ---------------- aggregation: one warp per destination node, no atomics ----------
__global__ void agg_kernel(float* __restrict__ out_x, float* __restrict__ out_t, int N) {
    int w    = blockIdx.x * (blockDim.x >> 5) + (threadIdx.x >> 5);
    int lane = threadIdx.x & 31;
    if (w >= N) return;
    int p0 = g_off[w];
    int p1 = g_off[w + 1];
    float stx = 0.f, sty = 0.f, stz = 0.f, stw = 0.f;
    float sxx = 0.f, sxy = 0.f, sxz = 0.f, sxw = 0.f;
    float da = 0.f, db = 0.f;
    for (int p = p0; p < p1; p++) {
        int eid = g_seid[p];
        int j   = g_scol[p];
        float ea = g_ea[eid];
        float eb = g_eb[eid];
        const float4 wt = *(const float4*)(g_wtp + (size_t)j * DD + lane * 4);
        const float4 wx = *(const float4*)(g_wxp + (size_t)j * DD + lane * 4);
        stx = fmaf(ea, wt.x, stx);
        sty = fmaf(ea, wt.y, sty);
        stz = fmaf(ea, wt.z, stz);
        stw = fmaf(ea, wt.w, stw);
        sxx = fmaf(eb, wx.x, sxx);
        sxy = fmaf(eb, wx.y, sxy);
        sxz = fmaf(eb, wx.z, sxz);
        sxw = fmaf(eb, wx.w, sxw);
        da += ea;
        db += eb;
    }
    float ia = (da > 0.f) ? 1.f / da : 0.f;
    float ib = (db > 0.f) ? 1.f / db : 0.f;
    *(float4*)(out_t + (size_t)w * DD + lane * 4) =
        make_float4(stx * ia, sty * ia, stz * ia, stw * ia);
    *(float4*)(out_x + (size_t)w * DD + lane * 4) =
        make_float4(sxx * ib, sxy * ib, sxz * ib, sxw * ib);
}

// ---------------- launch ----------------
extern "C" void kernel_launch(void* const* d_in, const int* in_sizes, int n_in,
                              void* d_out, int out_size) {
    const float* x    = (const float*)d_in[0];
    const float* t    = (const float*)d_in[1];
    const int*   ei   = (const int*)d_in[2];
    const float* W_x  = (const float*)d_in[3];
    const float* W_t  = (const float*)d_in[4];
    const float* Qa_w = (const float*)d_in[5];
    const float* Qa_b = (const float*)d_in[6];
    const float* Ka_w = (const float*)d_in[7];
    const float* Ka_b = (const float*)d_in[8];
    const float* Qb_w = (const float*)d_in[9];
    const float* Qb_b = (const float*)d_in[10];
    const float* Kb_w = (const float*)d_in[11];
    const float* Kb_b = (const float*)d_in[12];

    const int N = in_sizes[0] / DD;
    const int E = in_sizes[2] / 2;
    const int* rows = ei;
    const int* cols = ei + E;

    float* out_x = (float*)d_out;
    float* out_t = out_x + (size_t)N * DD;

    const int smem = (128 * 132 + 128 * 128) * (int)sizeof(float);
    cudaFuncSetAttribute(proj_kernel, cudaFuncAttributeMaxDynamicSharedMemorySize, smem);

    const int gb = (N + 127) / 128;
    proj_kernel<<<gb, 256, smem>>>(t, Qa_w, Qa_b, 0, N);
    proj_kernel<<<gb, 256, smem>>>(t, Ka_w, Ka_b, 1, N);
    proj_kernel<<<gb, 256, smem>>>(t, W_t, nullptr, 2, N);
    proj_kernel<<<gb, 256, smem>>>(x, Qb_w, Qb_b, 3, N);
    proj_kernel<<<gb, 256, smem>>>(x, Kb_w, Kb_b, 4, N);
    proj_kernel<<<gb, 256, smem>>>(x, W_x, nullptr, 5, N);

    zero_deg_kernel<<<(N + 255) / 256, 256>>>(N);
    count_deg_kernel<<<(E + 255) / 256, 256>>>(rows, E);
    scan_kernel<<<1, 1024>>>(N);
    scatter_kernel<<<(E + 255) / 256, 256>>>(rows, cols, E);
    scores_kernel<<<(E + 7) / 8, 256>>>(rows, cols, E);
    agg_kernel<<<(N + 7) / 8, 256>>>(out_x, out_t, N);
}

// round 2
// speedup vs baseline: 1.8942x; 1.8942x over previous
#include <cuda_runtime.h>
#include <cuda_bf16.h>
#include <stddef.h>

#define DD 128
#define PAD 132
#define NMAX 50176
#define EMAX 409600

// ---------------- device scratch ----------------
__device__ float g_qa[NMAX * DD];
__device__ float g_ka[NMAX * DD];
__device__ float g_qb[NMAX * DD];
__device__ float g_kb[NMAX * DD];
__device__ float g_wtp[NMAX * DD];
__device__ float g_wxp[NMAX * DD];
__device__ float g_wt[6 * DD * DD];   // pre-transposed weights [which][k][d]
__device__ float g_ea[EMAX];
__device__ float g_eb[EMAX];
__device__ int   g_deg[NMAX];
__device__ int   g_off[NMAX + 1];
__device__ int   g_cur[NMAX];
__device__ int   g_scol[EMAX];
__device__ int   g_seid[EMAX];

// ---------------- packed f32x2 helpers ----------------
__device__ __forceinline__ unsigned long long dup2(float v) {
    unsigned long long r;
    asm("mov.b64 %0, {%1, %1};" : "=l"(r) : "f"(v));
    return r;
}
__device__ __forceinline__ void fma2(unsigned long long& c, unsigned long long a,
                                     unsigned long long b) {
    asm("fma.rn.f32x2 %0, %1, %2, %0;" : "+l"(c) : "l"(a), "l"(b));
}
__device__ __forceinline__ float2 unpack2(unsigned long long v) {
    float2 r;
    asm("mov.b64 {%0, %1}, %2;" : "=f"(r.x), "=f"(r.y) : "l"(v));
    return r;
}

__device__ __forceinline__ float* dest_of(int which) {
    switch (which) {
        case 0: return g_qa;
        case 1: return g_ka;
        case 2: return g_wtp;
        case 3: return g_qb;
        case 4: return g_kb;
        default: return g_wxp;
    }
}

// ---------------- weight transpose: g_wt[which][k][d] = W[d][k] ----------------
__global__ void wtrans_kernel(const float* __restrict__ W0, const float* __restrict__ W1,
                              const float* __restrict__ W2, const float* __restrict__ W3,
                              const float* __restrict__ W4, const float* __restrict__ W5) {
    __shared__ float sm[DD * PAD];
    const float* W;
    switch (blockIdx.x) {
        case 0: W = W0; break;
        case 1: W = W1; break;
        case 2: W = W2; break;
        case 3: W = W3; break;
        case 4: W = W4; break;
        default: W = W5; break;
    }
    float* out = g_wt + blockIdx.x * (DD * DD);
    int tid = threadIdx.x;
    for (int t = tid; t < DD * 32; t += 256) {
        int r = t >> 5, kq = t & 31;
        float4 v = *(const float4*)(W + r * DD + kq * 4);
        *(float4*)(sm + r * PAD + kq * 4) = v;
    }
    __syncthreads();
    for (int t = tid; t < DD * 32; t += 256) {
        int k = t >> 5, dq = t & 31;
        float4 v = make_float4(sm[(4 * dq + 0) * PAD + k], sm[(4 * dq + 1) * PAD + k],
                               sm[(4 * dq + 2) * PAD + k], sm[(4 * dq + 3) * PAD + k]);
        *(float4*)(out + k * DD + dq * 4) = v;
    }
}

// ---------------- projection GEMM (merged, 6 outputs) ----------------
// Tile: 64 rows x 128 cols, K=128. 256 threads, micro-tile 2 rows x 16 cols
// (cols = {32q + 4*tc + s}). f32x2 packed accumulators. 2 CTAs/SM.
__global__ void __launch_bounds__(256, 2)
proj_kernel(const float* __restrict__ x, const float* __restrict__ t,
            const float* __restrict__ Qa_b, const float* __restrict__ Ka_b,
            const float* __restrict__ Qb_b, const float* __restrict__ Kb_b, int N) {
    extern __shared__ float sm[];
    float* ins = sm;            // [64][PAD]
    float* Ws  = sm + 64 * PAD; // [128][128] (k-major, pre-transposed)

    const int which = blockIdx.y;
    const float* in   = (which < 3) ? t : x;
    const float* bias;
    switch (which) {
        case 0: bias = Qa_b; break;
        case 1: bias = Ka_b; break;
        case 3: bias = Qb_b; break;
        case 4: bias = Kb_b; break;
        default: bias = nullptr; break;
    }
    const float* Wt = g_wt + which * (DD * DD);

    const int tid  = threadIdx.x;
    const int row0 = blockIdx.x * 64;

    // copy pre-transposed W into smem (conflict-free linear copy)
    for (int i = tid; i < DD * 32; i += 256)
        *(float4*)(Ws + i * 4) = *(const float4*)(Wt + i * 4);

    // load A tile
    for (int i = tid; i < 64 * 32; i += 256) {
        int r = i >> 5, kq = i & 31;
        int gr = row0 + r;
        float4 v = make_float4(0.f, 0.f, 0.f, 0.f);
        if (gr < N) v = *(const float4*)(in + (size_t)gr * DD + kq * 4);
        *(float4*)(ins + r * PAD + kq * 4) = v;
    }
    __syncthreads();

    const int tr = tid >> 3;  // 0..31 -> rows 2tr, 2tr+1
    const int tc = tid & 7;   // cols 32q + 4tc + s

    unsigned long long acc[2][4][2];
#pragma unroll
    for (int r = 0; r < 2; r++)
#pragma unroll
        for (int q = 0; q < 4; q++) acc[r][q][0] = acc[r][q][1] = 0ull;

    const float* a0p = ins + (2 * tr) * PAD;
    const float* a1p = a0p + PAD;
    const float* wp  = Ws + 4 * tc;

#pragma unroll 4
    for (int k = 0; k < DD; k += 2) {
        float2 a0 = *(const float2*)(a0p + k);
        float2 a1 = *(const float2*)(a1p + k);
        unsigned long long A00 = dup2(a0.x), A01 = dup2(a0.y);
        unsigned long long A10 = dup2(a1.x), A11 = dup2(a1.y);
#pragma unroll
        for (int q = 0; q < 4; q++) {
            ulonglong2 w0 = *(const ulonglong2*)(wp + k * DD + 32 * q);
            ulonglong2 w1 = *(const ulonglong2*)(wp + (k + 1) * DD + 32 * q);
            fma2(acc[0][q][0], A00, w0.x);
            fma2(acc[0][q][1], A00, w0.y);
            fma2(acc[1][q][0], A10, w0.x);
            fma2(acc[1][q][1], A10, w0.y);
            fma2(acc[0][q][0], A01, w1.x);
            fma2(acc[0][q][1], A01, w1.y);
            fma2(acc[1][q][0], A11, w1.x);
            fma2(acc[1][q][1], A11, w1.y);
        }
    }

    float bv[4][4];
#pragma unroll
    for (int q = 0; q < 4; q++) {
        if (bias != nullptr) {
            float4 b4 = *(const float4*)(bias + 32 * q + 4 * tc);
            bv[q][0] = b4.x; bv[q][1] = b4.y; bv[q][2] = b4.z; bv[q][3] = b4.w;
        } else {
            bv[q][0] = bv[q][1] = bv[q][2] = bv[q][3] = 0.f;
        }
    }

    float* out = dest_of(which);
#pragma unroll
    for (int r = 0; r < 2; r++) {
        int gr = row0 + 2 * tr + r;
        if (gr >= N) continue;
        float* op = out + (size_t)gr * DD + 4 * tc;
#pragma unroll
        for (int q = 0; q < 4; q++) {
            float2 u0 = unpack2(acc[r][q][0]);
            float2 u1 = unpack2(acc[r][q][1]);
            *(float4*)(op + 32 * q) = make_float4(u0.x + bv[q][0], u0.y + bv[q][1],
                                                  u1.x + bv[q][2], u1.y + bv[q][3]);
        }
    }
}

// ---------------- CSR construction ----------------
__global__ void zero_deg_kernel(int N) {
    int i = blockIdx.x * blockDim.x + threadIdx.x;
    if (i < N) g_deg[i] = 0;
}

__global__ void count_deg_kernel(const int* __restrict__ rows, int E) {
    int e = blockIdx.x * blockDim.x + threadIdx.x;
    if (e < E) atomicAdd(&g_deg[rows[e]], 1);
}

__global__ void scan_kernel(int N) {
    __shared__ int sh[1024];
    __shared__ int carry;
    int tid = threadIdx.x;
    if (tid == 0) carry = 0;
    __syncthreads();
    for (int base = 0; base < N; base += 1024) {
        int i = base + tid;
        int v = (i < N) ? g_deg[i] : 0;
        sh[tid] = v;
        __syncthreads();
        for (int off = 1; off < 1024; off <<= 1) {
            int tv = 0;
            if (tid >= off) tv = sh[tid - off];
            __syncthreads();
            if (tid >= off) sh[tid] += tv;
            __syncthreads();
        }
        int excl = sh[tid] - v;
        int c = carry;
        if (i < N) {
            g_off[i] = c + excl;
            g_cur[i] = c + excl;
        }
        int total = sh[1023];
        __syncthreads();
        if (tid == 0) carry = c + total;
        __syncthreads();
    }
    if (tid == 0) g_off[N] = carry;
}

__global__ void scatter_kernel(const int* __restrict__ rows, const int* __restrict__ cols,
                               int E) {
    int e = blockIdx.x * blockDim.x + threadIdx.x;
    if (e < E) {
        int p = atomicAdd(&g_cur[rows[e]], 1);
        g_scol[p] = cols[e];
        g_seid[p] = e;
    }
}

// ---------------- per-edge exp(score): one warp per edge ----------------
__global__ void scores_kernel(const int* __restrict__ rows, const int* __restrict__ cols,
                              int E) {
    int w    = blockIdx.x * (blockDim.x >> 5) + (threadIdx.x >> 5);
    int lane = threadIdx.x & 31;
    if (w >= E) return;
    int i = rows[w];
    int j = cols[w];
    const float4 qa = *(const float4*)(g_qa + (size_t)i * DD + lane * 4);
    const float4 ka = *(const float4*)(g_ka + (size_t)j * DD + lane * 4);
    const float4 qb = *(const float4*)(g_qb + (size_t)i * DD + lane * 4);
    const float4 kb = *(const float4*)(g_kb + (size_t)j * DD + lane * 4);
    float sa = qa.x * ka.x + qa.y * ka.y + qa.z * ka.z + qa.w * ka.w;
    float sb = qb.x * kb.x + qb.y * kb.y + qb.z * kb.z + qb.w * kb.w;
#pragma unroll
    for (int off = 16; off > 0; off >>= 1) {
        sa += __shfl_xor_sync(0xffffffffu, sa, off);
        sb += __shfl_xor_sync(0xffffffffu, sb, off);
    }
    if (lane == 0) {
        const float s = 0.08838834764831845f;  // 1/sqrt(128)
        g_ea[w] = expf(sa * s);
        g_eb[w] = expf(sb * s);
    }
}

// ---------------- aggregation: one warp per destination node, no atomics ----------
__global__ void agg_kernel(float* __restrict__ out_x, float* __restrict__ out_t, int N) {
    int w    = blockIdx.x * (blockDim.x >> 5) + (threadIdx.x >> 5);
    int lane = threadIdx.x & 31;
    if (w >= N) return;
    int p0 = g_off[w];
    int p1 = g_off[w + 1];
    float stx = 0.f, sty = 0.f, stz = 0.f, stw = 0.f;
    float sxx = 0.f, sxy = 0.f, sxz = 0.f, sxw = 0.f;
    float da = 0.f, db = 0.f;
    for (int p = p0; p < p1; p++) {
        int eid = g_seid[p];
        int j   = g_scol[p];
        float ea = g_ea[eid];
        float eb = g_eb[eid];
        const float4 wt = *(const float4*)(g_wtp + (size_t)j * DD + lane * 4);
        const float4 wx = *(const float4*)(g_wxp + (size_t)j * DD + lane * 4);
        stx = fmaf(ea, wt.x, stx);
        sty = fmaf(ea, wt.y, sty);
        stz = fmaf(ea, wt.z, stz);
        stw = fmaf(ea, wt.w, stw);
        sxx = fmaf(eb, wx.x, sxx);
        sxy = fmaf(eb, wx.y, sxy);
        sxz = fmaf(eb, wx.z, sxz);
        sxw = fmaf(eb, wx.w, sxw);
        da += ea;
        db += eb;
    }
    float ia = (da > 0.f) ? 1.f / da : 0.f;
    float ib = (db > 0.f) ? 1.f / db : 0.f;
    *(float4*)(out_t + (size_t)w * DD + lane * 4) =
        make_float4(stx * ia, sty * ia, stz * ia, stw * ia);
    *(float4*)(out_x + (size_t)w * DD + lane * 4) =
        make_float4(sxx * ib, sxy * ib, sxz * ib, sxw * ib);
}

// ---------------- launch ----------------
extern "C" void kernel_launch(void* const* d_in, const int* in_sizes, int n_in,
                              void* d_out, int out_size) {
    const float* x    = (const float*)d_in[0];
    const float* t    = (const float*)d_in[1];
    const int*   ei   = (const int*)d_in[2];
    const float* W_x  = (const float*)d_in[3];
    const float* W_t  = (const float*)d_in[4];
    const float* Qa_w = (const float*)d_in[5];
    const float* Qa_b = (const float*)d_in[6];
    const float* Ka_w = (const float*)d_in[7];
    const float* Ka_b = (const float*)d_in[8];
    const float* Qb_w = (const float*)d_in[9];
    const float* Qb_b = (const float*)d_in[10];
    const float* Kb_w = (const float*)d_in[11];
    const float* Kb_b = (const float*)d_in[12];

    const int N = in_sizes[0] / DD;
    const int E = in_sizes[2] / 2;
    const int* rows = ei;
    const int* cols = ei + E;

    float* out_x = (float*)d_out;
    float* out_t = out_x + (size_t)N * DD;

    // weight order: 0=Qa, 1=Ka, 2=W_t, 3=Qb, 4=Kb, 5=W_x
    wtrans_kernel<<<6, 256>>>(Qa_w, Ka_w, W_t, Qb_w, Kb_w, W_x);

    const int smem = (64 * PAD + DD * DD) * (int)sizeof(float);
    cudaFuncSetAttribute(proj_kernel, cudaFuncAttributeMaxDynamicSharedMemorySize, smem);
    dim3 pg((N + 63) / 64, 6);
    proj_kernel<<<pg, 256, smem>>>(x, t, Qa_b, Ka_b, Qb_b, Kb_b, N);

    zero_deg_kernel<<<(N + 255) / 256, 256>>>(N);
    count_deg_kernel<<<(E + 255) / 256, 256>>>(rows, E);
    scan_kernel<<<1, 1024>>>(N);
    scatter_kernel<<<(E + 255) / 256, 256>>>(rows, cols, E);
    scores_kernel<<<(E + 7) / 8, 256>>>(rows, cols, E);
    agg_kernel<<<(N + 7) / 8, 256>>>(out_x, out_t, N);
}

// round 3
// speedup vs baseline: 1.9966x; 1.0541x over previous
#include <cuda_runtime.h>
#include <cuda_bf16.h>
#include <stddef.h>

#define DD 128
#define PAD 132
#define NMAX 50176
#define EMAX 409600

// ---------------- device scratch ----------------
__device__ float g_qa[NMAX * DD];
__device__ float g_qb[NMAX * DD];
__device__ float g_wtp[NMAX * DD];
__device__ float g_wxp[NMAX * DD];
__device__ __nv_bfloat16 g_ka16[NMAX * DD];
__device__ __nv_bfloat16 g_kb16[NMAX * DD];
__device__ float g_wt[6 * DD * DD];   // pre-transposed weights [which][k][d]
__device__ int   g_deg[NMAX];
__device__ int   g_off[NMAX + 1];
__device__ int   g_cur[NMAX];
__device__ int   g_scol[EMAX];

// ---------------- packed f32x2 helpers ----------------
__device__ __forceinline__ unsigned long long dup2(float v) {
    unsigned long long r;
    asm("mov.b64 %0, {%1, %1};" : "=l"(r) : "f"(v));
    return r;
}
__device__ __forceinline__ void fma2(unsigned long long& c, unsigned long long a,
                                     unsigned long long b) {
    asm("fma.rn.f32x2 %0, %1, %2, %0;" : "+l"(c) : "l"(a), "l"(b));
}
__device__ __forceinline__ float2 unpack2(unsigned long long v) {
    float2 r;
    asm("mov.b64 {%0, %1}, %2;" : "=f"(r.x), "=f"(r.y) : "l"(v));
    return r;
}

// ---------------- weight transpose: g_wt[which][k][d] = W[d][k] ----------------
__global__ void wtrans_kernel(const float* __restrict__ W0, const float* __restrict__ W1,
                              const float* __restrict__ W2, const float* __restrict__ W3,
                              const float* __restrict__ W4, const float* __restrict__ W5) {
    __shared__ float sm[DD * PAD];
    const float* W;
    switch (blockIdx.x) {
        case 0: W = W0; break;
        case 1: W = W1; break;
        case 2: W = W2; break;
        case 3: W = W3; break;
        case 4: W = W4; break;
        default: W = W5; break;
    }
    float* out = g_wt + blockIdx.x * (DD * DD);
    int tid = threadIdx.x;
    for (int t = tid; t < DD * 32; t += 256) {
        int r = t >> 5, kq = t & 31;
        float4 v = *(const float4*)(W + r * DD + kq * 4);
        *(float4*)(sm + r * PAD + kq * 4) = v;
    }
    __syncthreads();
    for (int t = tid; t < DD * 32; t += 256) {
        int k = t >> 5, dq = t & 31;
        float4 v = make_float4(sm[(4 * dq + 0) * PAD + k], sm[(4 * dq + 1) * PAD + k],
                               sm[(4 * dq + 2) * PAD + k], sm[(4 * dq + 3) * PAD + k]);
        *(float4*)(out + k * DD + dq * 4) = v;
    }
}

// ---------------- projection GEMM (merged, 6 outputs) ----------------
// Tile: 64 rows x 128 cols, K=128. 256 threads, micro 2 rows x 16 cols.
// A tile in smem; W read from global (L1-resident, same-which CTAs contiguous).
__global__ void __launch_bounds__(256, 3)
proj_kernel(const float* __restrict__ x, const float* __restrict__ t,
            const float* __restrict__ Qa_b, const float* __restrict__ Ka_b,
            const float* __restrict__ Qb_b, const float* __restrict__ Kb_b, int N) {
    __shared__ float ins[64 * PAD];

    const int which = blockIdx.y;
    const float* in = (which < 3) ? t : x;
    const float* bias;
    switch (which) {
        case 0: bias = Qa_b; break;
        case 1: bias = Ka_b; break;
        case 3: bias = Qb_b; break;
        case 4: bias = Kb_b; break;
        default: bias = nullptr; break;
    }

    const int tid  = threadIdx.x;
    const int row0 = blockIdx.x * 64;

    for (int i = tid; i < 64 * 32; i += 256) {
        int r = i >> 5, kq = i & 31;
        int gr = row0 + r;
        float4 v = make_float4(0.f, 0.f, 0.f, 0.f);
        if (gr < N) v = *(const float4*)(in + (size_t)gr * DD + kq * 4);
        *(float4*)(ins + r * PAD + kq * 4) = v;
    }
    __syncthreads();

    const int tr = tid >> 3;  // rows 2tr, 2tr+1
    const int tc = tid & 7;   // cols 32q + 4tc + s

    unsigned long long acc[2][4][2];
#pragma unroll
    for (int r = 0; r < 2; r++)
#pragma unroll
        for (int q = 0; q < 4; q++) acc[r][q][0] = acc[r][q][1] = 0ull;

    const float* a0p = ins + (2 * tr) * PAD;
    const float* a1p = a0p + PAD;
    const float* wb  = g_wt + which * (DD * DD) + 4 * tc;

#pragma unroll 2
    for (int k = 0; k < DD; k += 2) {
        float2 a0 = *(const float2*)(a0p + k);
        float2 a1 = *(const float2*)(a1p + k);
        unsigned long long A00 = dup2(a0.x), A01 = dup2(a0.y);
        unsigned long long A10 = dup2(a1.x), A11 = dup2(a1.y);
#pragma unroll
        for (int q = 0; q < 4; q++) {
            ulonglong2 w0 = __ldg((const ulonglong2*)(wb + k * DD + 32 * q));
            ulonglong2 w1 = __ldg((const ulonglong2*)(wb + (k + 1) * DD + 32 * q));
            fma2(acc[0][q][0], A00, w0.x);
            fma2(acc[0][q][1], A00, w0.y);
            fma2(acc[1][q][0], A10, w0.x);
            fma2(acc[1][q][1], A10, w0.y);
            fma2(acc[0][q][0], A01, w1.x);
            fma2(acc[0][q][1], A01, w1.y);
            fma2(acc[1][q][0], A11, w1.x);
            fma2(acc[1][q][1], A11, w1.y);
        }
    }

    float bv[4][4];
#pragma unroll
    for (int q = 0; q < 4; q++) {
        if (bias != nullptr) {
            float4 b4 = *(const float4*)(bias + 32 * q + 4 * tc);
            bv[q][0] = b4.x; bv[q][1] = b4.y; bv[q][2] = b4.z; bv[q][3] = b4.w;
        } else {
            bv[q][0] = bv[q][1] = bv[q][2] = bv[q][3] = 0.f;
        }
    }

    const bool is_bf = (which == 1) || (which == 4);
    __nv_bfloat16* outb = (which == 1) ? g_ka16 : g_kb16;
    float* outf;
    switch (which) {
        case 0: outf = g_qa; break;
        case 2: outf = g_wtp; break;
        case 3: outf = g_qb; break;
        default: outf = g_wxp; break;
    }

#pragma unroll
    for (int r = 0; r < 2; r++) {
        int gr = row0 + 2 * tr + r;
        if (gr >= N) continue;
#pragma unroll
        for (int q = 0; q < 4; q++) {
            float2 u0 = unpack2(acc[r][q][0]);
            float2 u1 = unpack2(acc[r][q][1]);
            float o0 = u0.x + bv[q][0], o1 = u0.y + bv[q][1];
            float o2 = u1.x + bv[q][2], o3 = u1.y + bv[q][3];
            if (is_bf) {
                __nv_bfloat162 h0 = __floats2bfloat162_rn(o0, o1);
                __nv_bfloat162 h1 = __floats2bfloat162_rn(o2, o3);
                uint2 u;
                u.x = *(unsigned int*)&h0;
                u.y = *(unsigned int*)&h1;
                *(uint2*)(outb + (size_t)gr * DD + 32 * q + 4 * tc) = u;
            } else {
                *(float4*)(outf + (size_t)gr * DD + 32 * q + 4 * tc) =
                    make_float4(o0, o1, o2, o3);
            }
        }
    }
}

// ---------------- CSR construction ----------------
__global__ void zero_deg_kernel(int N) {
    int i = blockIdx.x * blockDim.x + threadIdx.x;
    if (i < N) g_deg[i] = 0;
}

__global__ void count_deg_kernel(const int* __restrict__ rows, int E) {
    int e = blockIdx.x * blockDim.x + threadIdx.x;
    if (e < E) atomicAdd(&g_deg[rows[e]], 1);
}

// single-block exclusive scan, shfl-based
__global__ void scan_kernel(int N) {
    __shared__ int wsum[32];
    __shared__ int carry;
    int tid = threadIdx.x, lane = tid & 31, wid = tid >> 5;
    if (tid == 0) carry = 0;
    __syncthreads();
    for (int base = 0; base < N; base += 1024) {
        int i = base + tid;
        int v = (i < N) ? g_deg[i] : 0;
        int s = v;
#pragma unroll
        for (int off = 1; off < 32; off <<= 1) {
            int u = __shfl_up_sync(0xffffffffu, s, off);
            if (lane >= off) s += u;
        }
        if (lane == 31) wsum[wid] = s;
        __syncthreads();
        if (wid == 0) {
            int ts = wsum[lane];
#pragma unroll
            for (int off = 1; off < 32; off <<= 1) {
                int u = __shfl_up_sync(0xffffffffu, ts, off);
                if (lane >= off) ts += u;
            }
            wsum[lane] = ts;
        }
        __syncthreads();
        int pre = carry + (wid > 0 ? wsum[wid - 1] : 0) + (s - v);
        if (i < N) {
            g_off[i] = pre;
            g_cur[i] = pre;
        }
        int total = wsum[31];
        __syncthreads();
        if (tid == 0) carry += total;
        __syncthreads();
    }
    if (tid == 0) g_off[N] = carry;
}

__global__ void scatter_kernel(const int* __restrict__ rows, const int* __restrict__ cols,
                               int E) {
    int e = blockIdx.x * blockDim.x + threadIdx.x;
    if (e < E) {
        int p = atomicAdd(&g_cur[rows[e]], 1);
        g_scol[p] = cols[e];
    }
}

// ---------------- fused scores + aggregation: one warp per dest node ----------------
__global__ void agg_kernel(float* __restrict__ out_x, float* __restrict__ out_t, int N) {
    int w    = blockIdx.x * (blockDim.x >> 5) + (threadIdx.x >> 5);
    int lane = threadIdx.x & 31;
    if (w >= N) return;
    int p0 = g_off[w];
    int p1 = g_off[w + 1];

    const float s = 0.08838834764831845f;  // 1/sqrt(128)
    float4 qa = *(const float4*)(g_qa + (size_t)w * DD + lane * 4);
    float4 qb = *(const float4*)(g_qb + (size_t)w * DD + lane * 4);
    qa.x *= s; qa.y *= s; qa.z *= s; qa.w *= s;
    qb.x *= s; qb.y *= s; qb.z *= s; qb.w *= s;

    float stx = 0.f, sty = 0.f, stz = 0.f, stw = 0.f;
    float sxx = 0.f, sxy = 0.f, sxz = 0.f, sxw = 0.f;
    float da = 0.f, db = 0.f;

    for (int p = p0; p < p1; p++) {
        int j = g_scol[p];
        // issue all gathers up front (independent of the reduce)
        uint2 kau = *(const uint2*)(g_ka16 + (size_t)j * DD + lane * 4);
        uint2 kbu = *(const uint2*)(g_kb16 + (size_t)j * DD + lane * 4);
        float4 wt = *(const float4*)(g_wtp + (size_t)j * DD + lane * 4);
        float4 wx = *(const float4*)(g_wxp + (size_t)j * DD + lane * 4);

        float2 ka0 = __bfloat1622float2(*(__nv_bfloat162*)&kau.x);
        float2 ka1 = __bfloat1622float2(*(__nv_bfloat162*)&kau.y);
        float2 kb0 = __bfloat1622float2(*(__nv_bfloat162*)&kbu.x);
        float2 kb1 = __bfloat1622float2(*(__nv_bfloat162*)&kbu.y);

        float sa = qa.x * ka0.x + qa.y * ka0.y + qa.z * ka1.x + qa.w * ka1.y;
        float sb = qb.x * kb0.x + qb.y * kb0.y + qb.z * kb1.x + qb.w * kb1.y;
#pragma unroll
        for (int off = 16; off > 0; off >>= 1) {
            sa += __shfl_xor_sync(0xffffffffu, sa, off);
            sb += __shfl_xor_sync(0xffffffffu, sb, off);
        }
        float ea = __expf(sa);
        float eb = __expf(sb);

        stx = fmaf(ea, wt.x, stx);
        sty = fmaf(ea, wt.y, sty);
        stz = fmaf(ea, wt.z, stz);
        stw = fmaf(ea, wt.w, stw);
        sxx = fmaf(eb, wx.x, sxx);
        sxy = fmaf(eb, wx.y, sxy);
        sxz = fmaf(eb, wx.z, sxz);
        sxw = fmaf(eb, wx.w, sxw);
        da += ea;
        db += eb;
    }
    float ia = (da > 0.f) ? 1.f / da : 0.f;
    float ib = (db > 0.f) ? 1.f / db : 0.f;
    *(float4*)(out_t + (size_t)w * DD + lane * 4) =
        make_float4(stx * ia, sty * ia, stz * ia, stw * ia);
    *(float4*)(out_x + (size_t)w * DD + lane * 4) =
        make_float4(sxx * ib, sxy * ib, sxz * ib, sxw * ib);
}

// ---------------- launch ----------------
extern "C" void kernel_launch(void* const* d_in, const int* in_sizes, int n_in,
                              void* d_out, int out_size) {
    const float* x    = (const float*)d_in[0];
    const float* t    = (const float*)d_in[1];
    const int*   ei   = (const int*)d_in[2];
    const float* W_x  = (const float*)d_in[3];
    const float* W_t  = (const float*)d_in[4];
    const float* Qa_w = (const float*)d_in[5];
    const float* Qa_b = (const float*)d_in[6];
    const float* Ka_w = (const float*)d_in[7];
    const float* Ka_b = (const float*)d_in[8];
    const float* Qb_w = (const float*)d_in[9];
    const float* Qb_b = (const float*)d_in[10];
    const float* Kb_w = (const float*)d_in[11];
    const float* Kb_b = (const float*)d_in[12];

    const int N = in_sizes[0] / DD;
    const int E = in_sizes[2] / 2;
    const int* rows = ei;
    const int* cols = ei + E;

    float* out_x = (float*)d_out;
    float* out_t = out_x + (size_t)N * DD;

    // weight order: 0=Qa, 1=Ka, 2=W_t, 3=Qb, 4=Kb, 5=W_x
    wtrans_kernel<<<6, 256>>>(Qa_w, Ka_w, W_t, Qb_w, Kb_w, W_x);

    zero_deg_kernel<<<(N + 255) / 256, 256>>>(N);
    count_deg_kernel<<<(E + 255) / 256, 256>>>(rows, E);
    scan_kernel<<<1, 1024>>>(N);
    scatter_kernel<<<(E + 255) / 256, 256>>>(rows, cols, E);

    dim3 pg((N + 63) / 64, 6);
    proj_kernel<<<pg, 256>>>(x, t, Qa_b, Ka_b, Qb_b, Kb_b, N);

    agg_kernel<<<(N + 7) / 8, 256>>>(out_x, out_t, N);
}

// round 5
// speedup vs baseline: 4.5547x; 2.2812x over previous
#include <cuda_runtime.h>
#include <cuda_bf16.h>
#include <stdint.h>
#include <stddef.h>

#define DD 128
#define NMAX 50176
#define EMAX 409600

// ---------------- device scratch ----------------
__device__ float g_qa[NMAX * DD];
__device__ float g_qb[NMAX * DD];
__device__ float g_wtp[NMAX * DD];
__device__ float g_wxp[NMAX * DD];
__device__ __nv_bfloat16 g_ka16[NMAX * DD];
__device__ __nv_bfloat16 g_kb16[NMAX * DD];
__device__ int   g_deg[NMAX];
__device__ int   g_off[NMAX + 1];
__device__ int   g_cur[NMAX];
__device__ int   g_scol[EMAX];
__device__ int   g_bsum[64];

// ---------------- cp.async helpers (portable, Ampere+) ----------------
__device__ __forceinline__ void cp_async16(uint32_t dst_smem, const void* src, int src_sz) {
    asm volatile("cp.async.cg.shared.global [%0], [%1], 16, %2;" ::
                 "r"(dst_smem), "l"(src), "r"(src_sz) : "memory");
}
#define CP_ASYNC_COMMIT() asm volatile("cp.async.commit_group;" ::: "memory")
#define CP_ASYNC_WAIT_ALL() asm volatile("cp.async.wait_group 0;" ::: "memory")

// ---------------- tf32 warp MMA ----------------
__device__ __forceinline__ void mma_tf32(float* c, uint32_t a0, uint32_t a1,
                                         uint32_t a2, uint32_t a3,
                                         uint32_t b0, uint32_t b1) {
    asm volatile(
        "mma.sync.aligned.m16n8k8.row.col.f32.tf32.tf32.f32 "
        "{%0,%1,%2,%3}, {%4,%5,%6,%7}, {%8,%9}, {%0,%1,%2,%3};"
        : "+f"(c[0]), "+f"(c[1]), "+f"(c[2]), "+f"(c[3])
        : "r"(a0), "r"(a1), "r"(a2), "r"(a3), "r"(b0), "r"(b1));
}

// smem layout (floats): A[128][132], B0[128][132], B1[128][132]
#define ROWF 132
#define TILE_F (128 * ROWF)
#define SMEM_FLOATS (3 * TILE_F)

// ---------------- fused tf32 projection GEMM ----------------
// grid (ceil(N/128), 2). y=0: input t, weights {Qa,Ka,W_t}; y=1: x, {Qb,Kb,W_x}.
// out rows [row0,row0+128): D = A @ W^T (+bias). W row-major [d][k] is exactly
// the col-major B (k x n) that mma.row.col wants.
__global__ void __launch_bounds__(256, 1)
proj_mma_kernel(const float* __restrict__ x, const float* __restrict__ t,
                const float* __restrict__ Qa_w, const float* __restrict__ Ka_w,
                const float* __restrict__ W_t,
                const float* __restrict__ Qb_w, const float* __restrict__ Kb_w,
                const float* __restrict__ W_x,
                const float* __restrict__ Qa_b, const float* __restrict__ Ka_b,
                const float* __restrict__ Qb_b, const float* __restrict__ Kb_b, int N) {
    extern __shared__ float sm[];
    float* As = sm;
    float* Bs[2] = {sm + TILE_F, sm + 2 * TILE_F};
    uint32_t sm_base = (uint32_t)__cvta_generic_to_shared(sm);

    const int tid  = threadIdx.x;
    const int wid  = tid >> 5;
    const int lane = tid & 31;
    const int y    = blockIdx.y;
    const int row0 = blockIdx.x * 128;

    const float* in = y ? x : t;
    const float* Ws[3];
    const float* Bias[3];
    Ws[0] = y ? Qb_w : Qa_w;
    Ws[1] = y ? Kb_w : Ka_w;
    Ws[2] = y ? W_x : W_t;
    Bias[0] = y ? Qb_b : Qa_b;
    Bias[1] = y ? Kb_b : Ka_b;
    Bias[2] = nullptr;
    float* dst_q = y ? g_qb : g_qa;
    float* dst_w = y ? g_wxp : g_wtp;
    __nv_bfloat16* dst_k = y ? g_kb16 : g_ka16;

    // ---- initial async loads: A tile + B0 (weight 0) ----
    // each thread copies 16 chunks of 16B; chunk c: row = c>>3, quad = c&7 ... use
    // linear mapping: 128 rows x 32 float4 per row = 4096 chunks, 256 threads -> 16 each
#pragma unroll
    for (int it = 0; it < 16; it++) {
        int c = tid + it * 256;
        int r = c >> 5, q4 = c & 31;
        int gr = row0 + r;
        uint32_t dst = sm_base + (uint32_t)((r * ROWF + q4 * 4) * 4);
        cp_async16(dst, in + (size_t)gr * DD + q4 * 4, gr < N ? 16 : 0);
    }
#pragma unroll
    for (int it = 0; it < 16; it++) {
        int c = tid + it * 256;
        int r = c >> 5, q4 = c & 31;
        uint32_t dst = sm_base + (uint32_t)((TILE_F + r * ROWF + q4 * 4) * 4);
        cp_async16(dst, Ws[0] + (size_t)r * DD + q4 * 4, 16);
    }
    CP_ASYNC_COMMIT();
    CP_ASYNC_WAIT_ALL();
    __syncthreads();

    const int warpM = (wid >> 1) * 32;   // 0,32,64,96
    const int warpN = (wid & 1) * 64;    // 0,64
    const int g = lane >> 2;             // 0..7
    const int tg = lane & 3;             // 0..3

    for (int w = 0; w < 3; w++) {
        // prefetch next weight into the other buffer
        if (w < 2) {
            int nb = (w + 1) & 1;
            const float* Wn = Ws[w + 1];
#pragma unroll
            for (int it = 0; it < 16; it++) {
                int c = tid + it * 256;
                int r = c >> 5, q4 = c & 31;
                uint32_t dst = sm_base +
                    (uint32_t)(((1 + nb) * TILE_F + r * ROWF + q4 * 4) * 4);
                cp_async16(dst, Wn + (size_t)r * DD + q4 * 4, 16);
            }
            CP_ASYNC_COMMIT();
        }

        const float* Bw = Bs[w & 1];
        float acc[2][8][4];
#pragma unroll
        for (int fm = 0; fm < 2; fm++)
#pragma unroll
            for (int fn = 0; fn < 8; fn++)
#pragma unroll
                for (int i = 0; i < 4; i++) acc[fm][fn][i] = 0.f;

        const float* Ap = As + (warpM + g) * ROWF + tg;
        const float* Bp = Bw + (warpN + g) * ROWF + tg;

#pragma unroll
        for (int ks = 0; ks < 16; ks++) {
            const int k = ks * 8;
            uint32_t a[2][4];
#pragma unroll
            for (int fm = 0; fm < 2; fm++) {
                const float* ap = Ap + fm * 16 * ROWF + k;
                a[fm][0] = __float_as_uint(ap[0]);
                a[fm][1] = __float_as_uint(ap[8 * ROWF]);
                a[fm][2] = __float_as_uint(ap[4]);
                a[fm][3] = __float_as_uint(ap[8 * ROWF + 4]);
            }
#pragma unroll
            for (int fn = 0; fn < 8; fn++) {
                const float* bp = Bp + fn * 8 * ROWF + k;
                uint32_t b0 = __float_as_uint(bp[0]);
                uint32_t b1 = __float_as_uint(bp[4]);
                mma_tf32(acc[0][fn], a[0][0], a[0][1], a[0][2], a[0][3], b0, b1);
                mma_tf32(acc[1][fn], a[1][0], a[1][1], a[1][2], a[1][3], b0, b1);
            }
        }

        // ---- epilogue ----
        const float* bias = Bias[w];
        float2 bv[8];
#pragma unroll
        for (int fn = 0; fn < 8; fn++) {
            int col = warpN + fn * 8 + 2 * tg;
            if (bias) bv[fn] = *(const float2*)(bias + col);
            else bv[fn] = make_float2(0.f, 0.f);
        }

#pragma unroll
        for (int fm = 0; fm < 2; fm++) {
            int m_lo = row0 + warpM + fm * 16 + g;
            int m_hi = m_lo + 8;
#pragma unroll
            for (int fn = 0; fn < 8; fn++) {
                int col = warpN + fn * 8 + 2 * tg;
                float o0 = acc[fm][fn][0] + bv[fn].x;
                float o1 = acc[fm][fn][1] + bv[fn].y;
                float o2 = acc[fm][fn][2] + bv[fn].x;
                float o3 = acc[fm][fn][3] + bv[fn].y;
                if (w == 1) {
                    if (m_lo < N) {
                        __nv_bfloat162 h = __floats2bfloat162_rn(o0, o1);
                        *(unsigned int*)(dst_k + (size_t)m_lo * DD + col) =
                            *(unsigned int*)&h;
                    }
                    if (m_hi < N) {
                        __nv_bfloat162 h = __floats2bfloat162_rn(o2, o3);
                        *(unsigned int*)(dst_k + (size_t)m_hi * DD + col) =
                            *(unsigned int*)&h;
                    }
                } else {
                    float* dst = (w == 0) ? dst_q : dst_w;
                    if (m_lo < N)
                        *(float2*)(dst + (size_t)m_lo * DD + col) = make_float2(o0, o1);
                    if (m_hi < N)
                        *(float2*)(dst + (size_t)m_hi * DD + col) = make_float2(o2, o3);
                }
            }
        }

        CP_ASYNC_WAIT_ALL();
        __syncthreads();
    }
}

// ---------------- CSR construction ----------------
__global__ void zero_deg_kernel(int N) {
    int i = blockIdx.x * blockDim.x + threadIdx.x;
    if (i < N) g_deg[i] = 0;
}

__global__ void count_deg_kernel(const int* __restrict__ rows, int E) {
    int e = blockIdx.x * blockDim.x + threadIdx.x;
    if (e < E) atomicAdd(&g_deg[rows[e]], 1);
}

// hierarchical scan: per-block local exclusive scan + block totals
__global__ void scan1_kernel(int N) {
    __shared__ int wsum[32];
    int tid = threadIdx.x, lane = tid & 31, wid = tid >> 5;
    int i = blockIdx.x * 1024 + tid;
    int v = (i < N) ? g_deg[i] : 0;
    int s = v;
#pragma unroll
    for (int off = 1; off < 32; off <<= 1) {
        int u = __shfl_up_sync(0xffffffffu, s, off);
        if (lane >= off) s += u;
    }
    if (lane == 31) wsum[wid] = s;
    __syncthreads();
    if (wid == 0) {
        int ts = wsum[lane];
#pragma unroll
        for (int off = 1; off < 32; off <<= 1) {
            int u = __shfl_up_sync(0xffffffffu, ts, off);
            if (lane >= off) ts += u;
        }
        wsum[lane] = ts;
    }
    __syncthreads();
    int excl = (wid > 0 ? wsum[wid - 1] : 0) + (s - v);
    if (i < N) g_off[i] = excl;
    if (tid == 1023) g_bsum[blockIdx.x] = wsum[31];
}

__global__ void scan2_kernel(int G, int N, int E) {
    if (threadIdx.x == 0) {
        int run = 0;
        for (int b = 0; b < G; b++) {
            int v = g_bsum[b];
            g_bsum[b] = run;
            run += v;
        }
        g_off[N] = E;
    }
}

__global__ void scan3_kernel(int N) {
    int i = blockIdx.x * 1024 + threadIdx.x;
    if (i < N) {
        int o = g_off[i] + g_bsum[blockIdx.x];
        g_off[i] = o;
        g_cur[i] = o;
    }
}

__global__ void scatter_kernel(const int* __restrict__ rows, const int* __restrict__ cols,
                               int E) {
    int e = blockIdx.x * blockDim.x + threadIdx.x;
    if (e < E) {
        int p = atomicAdd(&g_cur[rows[e]], 1);
        g_scol[p] = cols[e];
    }
}

// ---------------- fused scores + aggregation: one warp per dest node ----------------
__global__ void agg_kernel(float* __restrict__ out_x, float* __restrict__ out_t, int N) {
    int w    = blockIdx.x * (blockDim.x >> 5) + (threadIdx.x >> 5);
    int lane = threadIdx.x & 31;
    if (w >= N) return;
    int p0 = g_off[w];
    int p1 = g_off[w + 1];

    const float s = 0.08838834764831845f;  // 1/sqrt(128)
    float4 qa = *(const float4*)(g_qa + (size_t)w * DD + lane * 4);
    float4 qb = *(const float4*)(g_qb + (size_t)w * DD + lane * 4);
    qa.x *= s; qa.y *= s; qa.z *= s; qa.w *= s;
    qb.x *= s; qb.y *= s; qb.z *= s; qb.w *= s;

    float stx = 0.f, sty = 0.f, stz = 0.f, stw = 0.f;
    float sxx = 0.f, sxy = 0.f, sxz = 0.f, sxw = 0.f;
    float da = 0.f, db = 0.f;

    for (int p = p0; p < p1; p++) {
        int j = g_scol[p];
        uint2 kau = *(const uint2*)(g_ka16 + (size_t)j * DD + lane * 4);
        uint2 kbu = *(const uint2*)(g_kb16 + (size_t)j * DD + lane * 4);
        float4 wt = *(const float4*)(g_wtp + (size_t)j * DD + lane * 4);
        float4 wx = *(const float4*)(g_wxp + (size_t)j * DD + lane * 4);

        float2 ka0 = __bfloat1622float2(*(__nv_bfloat162*)&kau.x);
        float2 ka1 = __bfloat1622float2(*(__nv_bfloat162*)&kau.y);
        float2 kb0 = __bfloat1622float2(*(__nv_bfloat162*)&kbu.x);
        float2 kb1 = __bfloat1622float2(*(__nv_bfloat162*)&kbu.y);

        float sa = qa.x * ka0.x + qa.y * ka0.y + qa.z * ka1.x + qa.w * ka1.y;
        float sb = qb.x * kb0.x + qb.y * kb0.y + qb.z * kb1.x + qb.w * kb1.y;
#pragma unroll
        for (int off = 16; off > 0; off >>= 1) {
            sa += __shfl_xor_sync(0xffffffffu, sa, off);
            sb += __shfl_xor_sync(0xffffffffu, sb, off);
        }
        float ea = __expf(sa);
        float eb = __expf(sb);

        stx = fmaf(ea, wt.x, stx);
        sty = fmaf(ea, wt.y, sty);
        stz = fmaf(ea, wt.z, stz);
        stw = fmaf(ea, wt.w, stw);
        sxx = fmaf(eb, wx.x, sxx);
        sxy = fmaf(eb, wx.y, sxy);
        sxz = fmaf(eb, wx.z, sxz);
        sxw = fmaf(eb, wx.w, sxw);
        da += ea;
        db += eb;
    }
    float ia = (da > 0.f) ? 1.f / da : 0.f;
    float ib = (db > 0.f) ? 1.f / db : 0.f;
    *(float4*)(out_t + (size_t)w * DD + lane * 4) =
        make_float4(stx * ia, sty * ia, stz * ia, stw * ia);
    *(float4*)(out_x + (size_t)w * DD + lane * 4) =
        make_float4(sxx * ib, sxy * ib, sxz * ib, sxw * ib);
}

// ---------------- launch ----------------
extern "C" void kernel_launch(void* const* d_in, const int* in_sizes, int n_in,
                              void* d_out, int out_size) {
    const float* x    = (const float*)d_in[0];
    const float* t    = (const float*)d_in[1];
    const int*   ei   = (const int*)d_in[2];
    const float* W_x  = (const float*)d_in[3];
    const float* W_t  = (const float*)d_in[4];
    const float* Qa_w = (const float*)d_in[5];
    const float* Qa_b = (const float*)d_in[6];
    const float* Ka_w = (const float*)d_in[7];
    const float* Ka_b = (const float*)d_in[8];
    const float* Qb_w = (const float*)d_in[9];
    const float* Qb_b = (const float*)d_in[10];
    const float* Kb_w = (const float*)d_in[11];
    const float* Kb_b = (const float*)d_in[12];

    const int N = in_sizes[0] / DD;
    const int E = in_sizes[2] / 2;
    const int* rows = ei;
    const int* cols = ei + E;

    float* out_x = (float*)d_out;
    float* out_t = out_x + (size_t)N * DD;

    // CSR
    zero_deg_kernel<<<(N + 255) / 256, 256>>>(N);
    count_deg_kernel<<<(E + 255) / 256, 256>>>(rows, E);
    const int G = (N + 1023) / 1024;
    scan1_kernel<<<G, 1024>>>(N);
    scan2_kernel<<<1, 32>>>(G, N, E);
    scan3_kernel<<<G, 1024>>>(N);
    scatter_kernel<<<(E + 255) / 256, 256>>>(rows, cols, E);

    // projections via warp-level tf32 mma
    const int smem = SMEM_FLOATS * (int)sizeof(float);
    cudaFuncSetAttribute(proj_mma_kernel, cudaFuncAttributeMaxDynamicSharedMemorySize,
                         smem);
    dim3 pg((N + 127) / 128, 2);
    proj_mma_kernel<<<pg, 256, smem>>>(x, t, Qa_w, Ka_w, W_t, Qb_w, Kb_w, W_x,
                                       Qa_b, Ka_b, Qb_b, Kb_b, N);

    agg_kernel<<<(N + 7) / 8, 256>>>(out_x, out_t, N);
}